// round 8
// baseline (speedup 1.0000x reference)
#include <cuda_runtime.h>
#include <cuda_bf16.h>
#include <cstdint>

#define B_ 16
#define N_ 16384
#define CH 64
#define S_ 64
#define K_ 64
#define OUT1 (B_*128*N_)
#define OUT2 (OUT1 + B_*CH*S_)

__device__ float g_feaT[(size_t)B_ * N_ * CH];
__device__ float g_xnorm[B_ * N_];
__device__ float g_fploc[B_ * S_ * 3];
__device__ float g_fpfea[B_ * S_ * CH];
__device__ float g_nodeloc[B_ * S_ * 3];
__device__ float g_M[CH * CH];
__device__ float g_mu[CH];
__device__ float g_scale[CH];
__device__ float g_shift[CH];
__device__ float g_wT[CH * CH];

__device__ __forceinline__ float sq3_rn(float x, float y, float z) {
    return __fadd_rn(__fadd_rn(__fmul_rn(x, x), __fmul_rn(y, y)), __fmul_rn(z, z));
}

__global__ void k_zero() {
    int t = threadIdx.x;
    for (int j = t; j < CH * CH; j += 256) g_M[j] = 0.f;
    if (t < CH) g_mu[t] = 0.f;
}

__global__ __launch_bounds__(256) void k_xnorm(const float* __restrict__ loc) {
    int idx = blockIdx.x * 256 + threadIdx.x;
    int b = idx >> 14, n = idx & (N_ - 1);
    const float* lb = loc + (size_t)b * 3 * N_;
    g_xnorm[idx] = sq3_rn(lb[n], lb[N_ + n], lb[2 * N_ + n]);
}

__global__ __launch_bounds__(256) void k_transpose(const float* __restrict__ fea) {
    __shared__ float t[32][33];
    int b = blockIdx.z, c0 = blockIdx.y * 32, n0 = blockIdx.x * 32;
    int tx = threadIdx.x, ty = threadIdx.y;
    const float* src = fea + ((size_t)b * CH + c0) * N_ + n0;
#pragma unroll
    for (int k = 0; k < 4; k++) t[ty + k * 8][tx] = src[(size_t)(ty + k * 8) * N_ + tx];
    __syncthreads();
    float* dst = g_feaT + ((size_t)b * N_ + n0) * CH + c0;
#pragma unroll
    for (int k = 0; k < 4; k++) dst[(size_t)(ty + k * 8) * CH + tx] = t[tx][ty + k * 8];
}

__global__ __launch_bounds__(512) void k_fps(const float* __restrict__ loc) {
    extern __shared__ float s_dist[];
    __shared__ unsigned long long s_red[16];
    __shared__ int s_far;
    __shared__ int s_fidx[S_];
    __shared__ float s_c[3];
    int b = blockIdx.x, tid = threadIdx.x;
    const float* lx = loc + (size_t)b * 3 * N_;
    const float* ly = lx + N_;
    const float* lz = ly + N_;
    float px[32], py[32], pz[32];
#pragma unroll
    for (int i = 0; i < 32; i++) {
        int n = tid + i * 512;
        px[i] = lx[n]; py[i] = ly[n]; pz[i] = lz[n];
        s_dist[n] = 1e10f;
    }
    int far = 0;
    __syncthreads();
    for (int s = 0; s < S_; s++) {
        if (tid == 0) { s_fidx[s] = far; s_c[0] = lx[far]; s_c[1] = ly[far]; s_c[2] = lz[far]; }
        __syncthreads();
        float cx = s_c[0], cy = s_c[1], cz = s_c[2];
        unsigned long long best = 0ull;
#pragma unroll
        for (int i = 0; i < 32; i++) {
            int n = tid + i * 512;
            float dx = px[i] - cx, dy = py[i] - cy, dz = pz[i] - cz;
            float d = __fadd_rn(__fadd_rn(__fmul_rn(dx, dx), __fmul_rn(dy, dy)), __fmul_rn(dz, dz));
            float dm = fminf(s_dist[n], d);
            s_dist[n] = dm;
            unsigned long long key = ((unsigned long long)__float_as_uint(dm) << 32) |
                                     (unsigned)(0xFFFFFFFFu - (unsigned)n);
            if (key > best) best = key;
        }
#pragma unroll
        for (int off = 16; off; off >>= 1) {
            unsigned long long o = __shfl_down_sync(0xffffffffu, best, off);
            if (o > best) best = o;
        }
        if ((tid & 31) == 0) s_red[tid >> 5] = best;
        __syncthreads();
        if (tid < 32) {
            unsigned long long v = (tid < 16) ? s_red[tid] : 0ull;
#pragma unroll
            for (int off = 8; off; off >>= 1) {
                unsigned long long o = __shfl_down_sync(0xffffffffu, v, off);
                if (o > v) v = o;
            }
            if (tid == 0) s_far = (int)(0xFFFFFFFFu - (unsigned)(v & 0xFFFFFFFFull));
        }
        __syncthreads();
        far = s_far;
        __syncthreads();
    }
    if (tid < S_) {
        int n = s_fidx[tid];
        g_fploc[(b * S_ + tid) * 3 + 0] = lx[n];
        g_fploc[(b * S_ + tid) * 3 + 1] = ly[n];
        g_fploc[(b * S_ + tid) * 3 + 2] = lz[n];
    }
    __syncthreads();
    for (int j = tid; j < S_ * CH; j += 512) {
        int s = j >> 6, c = j & 63;
        g_fpfea[b * S_ * CH + j] = g_feaT[((size_t)(b * N_ + s_fidx[s])) * CH + c];
    }
}

__global__ __launch_bounds__(128) void k_ball(const float* __restrict__ loc,
                                              const float* __restrict__ w_off,
                                              float* __restrict__ out) {
    __shared__ int   s_idx[K_];
    __shared__ float s_fpf[CH];
    __shared__ float s_w[3 * CH];
    __shared__ float s_p[3];
    __shared__ int   s_cnt;
    __shared__ float s_part[2][3];
    int s = blockIdx.x, b = blockIdx.y, tid = threadIdx.x;
    for (int j = tid; j < 3 * CH; j += 128) s_w[j] = w_off[j];
    if (tid < CH) s_fpf[tid] = g_fpfea[(b * S_ + s) * CH + tid];
    if (tid < 3) s_p[tid] = g_fploc[(b * S_ + s) * 3 + tid];
    if (tid == 0) s_cnt = 0;
    __syncthreads();
    float px = s_p[0], py = s_p[1], pz = s_p[2];
    float pp = sq3_rn(px, py, pz);
    if (tid < 32) {
        const float R2 = 0.3f * 0.3f;
        const float* lx = loc + (size_t)b * 3 * N_;
        const float* ly = lx + N_;
        const float* lz = ly + N_;
        const float* xn = g_xnorm + b * N_;
        int cnt = 0;
        for (int base = 0; base < N_ && cnt < K_; base += 32) {
            int n = base + tid;
            float dot = fmaf(pz, lz[n], fmaf(py, ly[n], __fmul_rn(px, lx[n])));
            float sqv = __fadd_rn(__fadd_rn(__fmul_rn(-2.0f, dot), pp), xn[n]);
            bool in = !(sqv > R2);
            unsigned m = __ballot_sync(0xffffffffu, in);
            int pos = cnt + __popc(m & ((1u << tid) - 1u));
            if (in && pos < K_) s_idx[pos] = n;
            cnt += __popc(m);
        }
        if (tid == 0) s_cnt = cnt < K_ ? cnt : K_;
    }
    __syncthreads();
    int cnt = s_cnt;
    if (tid >= cnt && tid < K_) s_idx[tid] = s_idx[0];
    __syncthreads();
    float c0 = 0.f, c1 = 0.f, c2 = 0.f;
    if (tid < K_) {
        int n = s_idx[tid];
        const float4* fr = (const float4*)(g_feaT + ((size_t)(b * N_ + n)) * CH);
        float a0 = 0.f, a1 = 0.f, a2 = 0.f;
#pragma unroll
        for (int j = 0; j < 16; j++) {
            float4 f = fr[j];
            float g0 = f.x - s_fpf[4 * j + 0];
            float g1 = f.y - s_fpf[4 * j + 1];
            float g2 = f.z - s_fpf[4 * j + 2];
            float g3 = f.w - s_fpf[4 * j + 3];
            a0 = fmaf(s_w[4 * j + 0], g0, a0); a0 = fmaf(s_w[4 * j + 1], g1, a0);
            a0 = fmaf(s_w[4 * j + 2], g2, a0); a0 = fmaf(s_w[4 * j + 3], g3, a0);
            a1 = fmaf(s_w[CH + 4 * j + 0], g0, a1); a1 = fmaf(s_w[CH + 4 * j + 1], g1, a1);
            a1 = fmaf(s_w[CH + 4 * j + 2], g2, a1); a1 = fmaf(s_w[CH + 4 * j + 3], g3, a1);
            a2 = fmaf(s_w[2 * CH + 4 * j + 0], g0, a2); a2 = fmaf(s_w[2 * CH + 4 * j + 1], g1, a2);
            a2 = fmaf(s_w[2 * CH + 4 * j + 2], g2, a2); a2 = fmaf(s_w[2 * CH + 4 * j + 3], g3, a2);
        }
        float t0 = tanhf(a0), t1 = tanhf(a1), t2 = tanhf(a2);
        const float* lp = loc + (size_t)b * 3 * N_;
        c0 = t0 * (lp[n] - px);
        c1 = t1 * (lp[N_ + n] - py);
        c2 = t2 * (lp[2 * N_ + n] - pz);
    }
#pragma unroll
    for (int off = 16; off; off >>= 1) {
        c0 += __shfl_down_sync(0xffffffffu, c0, off);
        c1 += __shfl_down_sync(0xffffffffu, c1, off);
        c2 += __shfl_down_sync(0xffffffffu, c2, off);
    }
    if (tid < K_ && (tid & 31) == 0) {
        s_part[tid >> 5][0] = c0; s_part[tid >> 5][1] = c1; s_part[tid >> 5][2] = c2;
    }
    __syncthreads();
    if (tid == 0) {
        float o0 = (s_part[0][0] + s_part[1][0]) * 0.015625f;
        float o1 = (s_part[0][1] + s_part[1][1]) * 0.015625f;
        float o2 = (s_part[0][2] + s_part[1][2]) * 0.015625f;
        out[OUT2 + b * 3 * S_ + 0 * S_ + s] = o0;
        out[OUT2 + b * 3 * S_ + 1 * S_ + s] = o1;
        out[OUT2 + b * 3 * S_ + 2 * S_ + s] = o2;
        g_nodeloc[(b * S_ + s) * 3 + 0] = px + o0;
        g_nodeloc[(b * S_ + s) * 3 + 1] = py + o1;
        g_nodeloc[(b * S_ + s) * 3 + 2] = pz + o2;
    }
}

__global__ __launch_bounds__(256) void k_moments() {
    __shared__ float tile[128 * CH];
    int blk = blockIdx.x;
    int b = blk >> 4;
    int p0 = (blk & 15) * 1024;
    int tid = threadIdx.x;
    int r0 = (tid >> 4) << 2, c0 = (tid & 15) << 2;
    float acc[16];
#pragma unroll
    for (int i = 0; i < 16; i++) acc[i] = 0.f;
    float mu = 0.f;
    for (int t = 0; t < 8; t++) {
        const float4* src = (const float4*)(g_feaT + ((size_t)(b * N_ + p0 + t * 128)) * CH);
        float4* dst4 = (float4*)tile;
        for (int j = tid; j < 128 * CH / 4; j += 256) dst4[j] = src[j];
        __syncthreads();
        for (int p = 0; p < 128; p++) {
            float4 av = *(const float4*)&tile[p * CH + r0];
            float4 bv = *(const float4*)&tile[p * CH + c0];
            acc[0]  = fmaf(av.x, bv.x, acc[0]);  acc[1]  = fmaf(av.x, bv.y, acc[1]);
            acc[2]  = fmaf(av.x, bv.z, acc[2]);  acc[3]  = fmaf(av.x, bv.w, acc[3]);
            acc[4]  = fmaf(av.y, bv.x, acc[4]);  acc[5]  = fmaf(av.y, bv.y, acc[5]);
            acc[6]  = fmaf(av.y, bv.z, acc[6]);  acc[7]  = fmaf(av.y, bv.w, acc[7]);
            acc[8]  = fmaf(av.z, bv.x, acc[8]);  acc[9]  = fmaf(av.z, bv.y, acc[9]);
            acc[10] = fmaf(av.z, bv.z, acc[10]); acc[11] = fmaf(av.z, bv.w, acc[11]);
            acc[12] = fmaf(av.w, bv.x, acc[12]); acc[13] = fmaf(av.w, bv.y, acc[13]);
            acc[14] = fmaf(av.w, bv.z, acc[14]); acc[15] = fmaf(av.w, bv.w, acc[15]);
        }
        if (tid < CH)
            for (int p = 0; p < 128; p++) mu += tile[p * CH + tid];
        __syncthreads();
    }
#pragma unroll
    for (int i = 0; i < 4; i++)
#pragma unroll
        for (int j = 0; j < 4; j++)
            atomicAdd(&g_M[(r0 + i) * CH + (c0 + j)], acc[i * 4 + j]);
    if (tid < CH) atomicAdd(&g_mu[tid], mu);
}

__global__ __launch_bounds__(256) void k_bn(const float* __restrict__ w,
                                            const float* __restrict__ b_res,
                                            const float* __restrict__ g_res,
                                            const float* __restrict__ be_res) {
    __shared__ float sM[CH * CH];
    __shared__ float sw[CH * CH];
    __shared__ float smu[CH];
    int tid = threadIdx.x;
    for (int j = tid; j < CH * CH; j += 256) { sM[j] = g_M[j]; sw[j] = w[j]; }
    if (tid < CH) smu[tid] = g_mu[tid];
    __syncthreads();
    const float invNp = 1.0f / (float)((size_t)B_ * N_);
    if (tid < CH) {
        int o = tid;
        float m1 = 0.f, ey2 = 0.f;
        for (int c = 0; c < CH; c++) {
            float wc = sw[o * CH + c];
            m1 = fmaf(wc, smu[c], m1);
            float r = 0.f;
            for (int c2 = 0; c2 < CH; c2++) r = fmaf(sw[o * CH + c2], sM[c * CH + c2], r);
            ey2 = fmaf(wc, r, ey2);
        }
        m1 *= invNp; ey2 *= invNp;
        float var = ey2 - m1 * m1;
        float meanY = m1 + b_res[o];
        float sc = rsqrtf(var + 1e-5f) * g_res[o];
        g_scale[o] = sc;
        g_shift[o] = fmaf(b_res[o] - meanY, sc, be_res[o]);
    }
    for (int j = tid; j < CH * CH; j += 256) {
        int c = j >> 6, o = j & 63;
        g_wT[c * CH + o] = sw[o * CH + c];
    }
}

__global__ __launch_bounds__(256) void k_knn(const float* __restrict__ loc,
                                             float* __restrict__ out) {
    extern __shared__ float s_dyn[];               // 16384 floats (64KB)
    unsigned* s_keys = (unsigned*)s_dyn;
    __shared__ int sH[256];
    __shared__ int sScan[256];
    __shared__ unsigned sPref;
    __shared__ int sWant, sC1, sCT;
    __shared__ int s_out[K_];
    __shared__ int s_tie[128];
    __shared__ float s_red[4 * CH];
    int s = blockIdx.x, b = blockIdx.y, tid = threadIdx.x;
    float qx = g_nodeloc[(b * S_ + s) * 3 + 0];
    float qy = g_nodeloc[(b * S_ + s) * 3 + 1];
    float qz = g_nodeloc[(b * S_ + s) * 3 + 2];
    float qq = sq3_rn(qx, qy, qz);
    const float* lx = loc + (size_t)b * 3 * N_;
    const float* ly = lx + N_;
    const float* lz = ly + N_;
    const float* xn = g_xnorm + b * N_;
    for (int i = 0; i < 64; i++) {
        int n = tid + i * 256;
        float dot = fmaf(qz, lz[n], fmaf(qy, ly[n], __fmul_rn(qx, lx[n])));
        float d = __fadd_rn(__fadd_rn(__fmul_rn(-2.0f, dot), qq), xn[n]);
        unsigned u = __float_as_uint(d);
        u = (u & 0x80000000u) ? ~u : (u | 0x80000000u);
        s_keys[n] = u;
    }
    if (tid == 0) { sPref = 0u; sWant = K_; sC1 = 0; sCT = 0; }
    __syncthreads();
    for (int p = 3; p >= 0; p--) {
        int sh = p * 8;
        sH[tid] = 0;
        __syncthreads();
        unsigned himask = (p == 3) ? 0u : (0xFFFFFFFFu << (sh + 8));
        unsigned pref = sPref;
        for (int i = 0; i < 64; i++) {
            unsigned k = s_keys[tid + i * 256];
            if ((k & himask) == pref) atomicAdd(&sH[(k >> sh) & 255], 1);
        }
        __syncthreads();
        int v = sH[tid];
        sScan[tid] = v;
        __syncthreads();
        for (int off = 1; off < 256; off <<= 1) {
            int t = (tid >= off) ? sScan[tid - off] : 0;
            __syncthreads();
            sScan[tid] += t;
            __syncthreads();
        }
        int excl = sScan[tid] - v;
        int want = sWant;
        if (excl < want && want <= excl + v) {
            sPref = pref | ((unsigned)tid << sh);
            sWant = want - excl;
        }
        __syncthreads();
    }
    unsigned pivot = sPref;
    int need = sWant;
    for (int i = 0; i < 64; i++) {
        int n = tid + i * 256;
        unsigned k = s_keys[n];
        if (k < pivot) { int p0 = atomicAdd(&sC1, 1); s_out[p0] = n; }
        else if (k == pivot) { int p0 = atomicAdd(&sCT, 1); if (p0 < 128) s_tie[p0] = n; }
    }
    __syncthreads();
    if (tid == 0) {
        int c1 = sC1, nt = sCT; if (nt > 128) nt = 128;
        for (int j = 0; j < need; j++) {
            int bi = -1, bv = 0x7fffffff;
            for (int t = 0; t < nt; t++) { int v2 = s_tie[t]; if (v2 >= 0 && v2 < bv) { bv = v2; bi = t; } }
            s_out[c1 + j] = bv;
            if (bi >= 0) s_tie[bi] = -1;
        }
    }
    __syncthreads();
    // ---- gather + GEMM + kmax + BN/relu ----
    float* xg = s_dyn;                 // [64][64]
    float* sWT = s_dyn + 4096;         // [c][o]
    for (int j = tid; j < 1024; j += 256) {
        int r = j >> 4, c4 = j & 15;
        float4 f = ((const float4*)(g_feaT + ((size_t)(b * N_ + s_out[r])) * CH))[c4];
        ((float4*)xg)[j] = f;
        ((float4*)sWT)[j] = ((const float4*)g_wT)[j];
    }
    __syncthreads();
    int o = tid & 63, kseg = tid >> 6;
    float wreg[64];
#pragma unroll
    for (int c = 0; c < 64; c++) wreg[c] = sWT[c * 64 + o];
    float mx = -3.4e38f;
    for (int k = kseg * 16; k < kseg * 16 + 16; k++) {
        const float4* xr4 = (const float4*)(xg + (k << 6));
        float acc = 0.f;
#pragma unroll
        for (int c = 0; c < 16; c++) {
            float4 f = xr4[c];
            acc = fmaf(wreg[4 * c + 0], f.x, acc);
            acc = fmaf(wreg[4 * c + 1], f.y, acc);
            acc = fmaf(wreg[4 * c + 2], f.z, acc);
            acc = fmaf(wreg[4 * c + 3], f.w, acc);
        }
        mx = fmaxf(mx, acc);
    }
    s_red[kseg * 64 + o] = mx;
    __syncthreads();
    if (tid < 64) {
        float m = fmaxf(fmaxf(s_red[tid], s_red[64 + tid]), fmaxf(s_red[128 + tid], s_red[192 + tid]));
        float val = fmaxf(fmaf(m, g_scale[tid], g_shift[tid]), 0.f);
        out[OUT1 + (b * CH + tid) * S_ + s] = val;
    }
}

__global__ __launch_bounds__(256) void k_up(const float* __restrict__ loc,
                                            const float* __restrict__ fea,
                                            float* __restrict__ out) {
    __shared__ float nx[64], ny[64], nz[64], nn[64];
    __shared__ float nf[64 * 65];
    int b = blockIdx.y, n0 = blockIdx.x * 256, tid = threadIdx.x;
    if (tid < 64) {
        float x = g_nodeloc[(b * S_ + tid) * 3 + 0];
        float y = g_nodeloc[(b * S_ + tid) * 3 + 1];
        float z = g_nodeloc[(b * S_ + tid) * 3 + 2];
        nx[tid] = x; ny[tid] = y; nz[tid] = z; nn[tid] = sq3_rn(x, y, z);
    }
    for (int j = tid; j < 64 * 64; j += 256) {
        int c = j >> 6, s2 = j & 63;
        nf[c * 65 + s2] = out[OUT1 + (b * CH + c) * S_ + s2];
    }
    __syncthreads();
    int n = n0 + tid;
    const float* lp = loc + (size_t)b * 3 * N_;
    float px = lp[n], py = lp[N_ + n], pz = lp[2 * N_ + n];
    float pn = g_xnorm[b * N_ + n];
    float d0 = 3.4e38f, d1 = 3.4e38f, d2 = 3.4e38f;
    int i0 = 0, i1 = 0, i2 = 0;
    for (int s2 = 0; s2 < 64; s2++) {
        float dot = fmaf(pz, nz[s2], fmaf(py, ny[s2], __fmul_rn(px, nx[s2])));
        float d = __fadd_rn(__fadd_rn(__fmul_rn(-2.0f, dot), pn), nn[s2]);
        if (d < d0)      { d2 = d1; i2 = i1; d1 = d0; i1 = i0; d0 = d; i0 = s2; }
        else if (d < d1) { d2 = d1; i2 = i1; d1 = d; i1 = s2; }
        else if (d < d2) { d2 = d; i2 = s2; }
    }
    float w0 = 1.0f / fmaxf(d0, 1e-10f);
    float w1 = 1.0f / fmaxf(d1, 1e-10f);
    float w2 = 1.0f / fmaxf(d2, 1e-10f);
    float ws = __fadd_rn(__fadd_rn(w0, w1), w2);
    w0 /= ws; w1 /= ws; w2 /= ws;
    const float* fb = fea + (size_t)b * CH * N_ + n;
    float* ob = out + (size_t)b * 128 * N_ + n;
#pragma unroll 8
    for (int c = 0; c < 64; c++) ob[(size_t)c * N_] = fb[(size_t)c * N_];
#pragma unroll 8
    for (int c = 0; c < 64; c++) {
        float v = fmaf(nf[c * 65 + i2], w2, fmaf(nf[c * 65 + i1], w1, __fmul_rn(nf[c * 65 + i0], w0)));
        ob[(size_t)(64 + c) * N_] = v;
    }
}

extern "C" void kernel_launch(void* const* d_in, const int* in_sizes, int n_in,
                              void* d_out, int out_size) {
    const float* fea   = (const float*)d_in[0];
    const float* loc   = (const float*)d_in[1];
    const float* w_res = (const float*)d_in[2];
    const float* b_res = (const float*)d_in[3];
    const float* g_res = (const float*)d_in[4];
    const float* be_res= (const float*)d_in[5];
    const float* w_off = (const float*)d_in[6];
    float* out = (float*)d_out;

    cudaFuncSetAttribute(k_fps, cudaFuncAttributeMaxDynamicSharedMemorySize, 65536);
    cudaFuncSetAttribute(k_knn, cudaFuncAttributeMaxDynamicSharedMemorySize, 65536);

    k_zero<<<1, 256>>>();
    k_xnorm<<<(B_ * N_) / 256, 256>>>(loc);
    k_transpose<<<dim3(N_ / 32, CH / 32, B_), dim3(32, 8)>>>(fea);
    k_fps<<<B_, 512, 65536>>>(loc);
    k_ball<<<dim3(S_, B_), 128>>>(loc, w_off, out);
    k_moments<<<256, 256>>>();
    k_bn<<<1, 256>>>(w_res, b_res, g_res, be_res);
    k_knn<<<dim3(S_, B_), 256, 65536>>>(loc, out);
    k_up<<<dim3(N_ / 256, B_), 256>>>(loc, fea, out);
}